// round 13
// baseline (speedup 1.0000x reference)
#include <cuda_runtime.h>
#include <math.h>

// Problem constants
#define BB 4096
#define KK 64
#define FF 128
#define TE 32
#define DD 160
#define NT 10000
#define INV_SQRT_D 0.07905694150420949f   // 1/sqrt(160)
#define FULL 0xffffffffu

// ---------------- scratch (__device__ globals) ----------------------------------
__device__ __align__(16) float g_tbl[NT * TE];   // cos(t*w+b) table
__device__ __align__(16) float g_Mt[DD * DD];    // Mt[g][o] = (Wk^T Wq / sqrt(D))[o][g]
__device__ __align__(16) float g_Pt[DD * DD];    // Pt[g][e] = (out_w @ Wv)[e][g]
__device__ float g_m0[DD];
__device__ float g_w0[DD];
__device__ float g_p0[DD];
__device__ float g_b00[1];

// ---------------- kernel 0: fold weights + cos table (merged) --------------------
#define PREP_BLKS (2 * DD + 1)
__global__ void __launch_bounds__(256)
setup_kernel(const float* __restrict__ ipw,
             const float* __restrict__ ipb,
             const float* __restrict__ outw,
             const float* __restrict__ outb,
             const float* __restrict__ tw,
             const float* __restrict__ tb) {
    int bidx = blockIdx.x;
    int t = threadIdx.x;
    if (bidx < PREP_BLKS) {
        if (t >= DD) return;
        if (bidx < DD) {
            int f = bidx;
            float acc = 0.f;
            for (int d = 0; d < DD; ++d)
                acc = fmaf(ipw[(DD + d) * DD + f], ipw[d * DD + t], acc);
            g_Mt[t * DD + f] = acc * INV_SQRT_D;           // transposed
        } else if (bidx < 2 * DD) {
            int e = bidx - DD;
            float acc = 0.f;
            for (int d = 0; d < DD; ++d)
                acc = fmaf(outw[e * DD + d], ipw[(2 * DD + d) * DD + t], acc);
            g_Pt[t * DD + e] = acc;                        // transposed
        } else {
            float m0 = 0.f, w0 = 0.f, p0 = 0.f;
            for (int d = 0; d < DD; ++d) {
                m0 = fmaf(ipw[(DD + d) * DD + t], ipb[d], m0);
                w0 = fmaf(ipw[d * DD + t], ipb[DD + d], w0);
                p0 = fmaf(outw[t * DD + d], ipb[2 * DD + d], p0);
            }
            g_m0[t] = m0 * INV_SQRT_D;
            g_w0[t] = w0 * INV_SQRT_D;
            g_p0[t] = p0 + outb[t];
            if (t == 0) {
                float b00 = 0.f;
                for (int d = 0; d < DD; ++d) b00 = fmaf(ipb[d], ipb[DD + d], b00);
                g_b00[0] = b00 * INV_SQRT_D;
            }
        }
    } else {
        int idx = (bidx - PREP_BLKS) * 256 + t;
        if (idx >= NT * TE) return;
        int tt = idx >> 5;
        int j = idx & 31;
        float arg = __fadd_rn(__fmul_rn((float)tt, tw[j]), tb[j]);
        float kf = rintf(arg * 0.15915494309189535f);
        double r = fma(-(double)kf, 6.283185307179586, (double)arg);
        g_tbl[idx] = cosf((float)r);
    }
}

// ---------------- fused mega-kernel ----------------------------------------------
// grid 512 x 256 thr; 8 targets/block, warp w owns target blockIdx*8+w.
// All intermediates warp-private; only the streamed B chunk buffer is shared.
__global__ void __launch_bounds__(256, 3)
fused_kernel(const float* __restrict__ x,
             const int* __restrict__ tgt_ids,
             const int* __restrict__ tgt_times,
             const int* __restrict__ nbr_ids,
             const int* __restrict__ etime,
             const float* __restrict__ gum,
             const float* __restrict__ ew,
             const float* __restrict__ mlpw,
             const float* __restrict__ mlpb,
             float* __restrict__ out1,
             float* __restrict__ out2,
             float* __restrict__ out_mask) {
    __shared__ __align__(16) float sQ[8][DD];          // q_in rows; recycled as Acc rows
    __shared__ __align__(16) float sU[8][DD];          // transformed queries
    __shared__ __align__(16) float sBs[2][16][DD];     // streamed B chunks
    __shared__ __align__(16) float sw0[DD];
    __shared__ float smlp[DD + 2];
    __shared__ float sb00;

    int t = threadIdx.x, w = t >> 5, lane = t & 31;
    int b = blockIdx.x * 8 + w;

    if (t < DD) sw0[t] = g_w0[t];
    if (t < DD + 1) smlp[t] = mlpw[t];
    if (t == 0) { smlp[DD + 1] = mlpb[0]; sb00 = g_b00[0]; }
    __syncthreads();

    const float4* xv = (const float4*)x;
    const float4* tv = (const float4*)g_tbl;

    // ---- gather q_in row + S0 (warp-private) ----
    int tg = tgt_ids[b], ttm = tgt_times[b];
    float4 q4 = xv[tg * 32 + lane];
    ((float4*)sQ[w])[lane] = q4;
    float4 w04 = ((const float4*)sw0)[lane];
    float s0p = q4.x * w04.x + q4.y * w04.y + q4.z * w04.z + q4.w * w04.w;
    if (lane < 8) {
        float4 te4 = tv[ttm * 8 + lane];
        ((float4*)sQ[w])[32 + lane] = te4;
        float4 wt4 = ((const float4*)sw0)[32 + lane];
        s0p += te4.x * wt4.x + te4.y * wt4.y + te4.z * wt4.z + te4.w * wt4.w;
    }
#pragma unroll
    for (int o = 16; o; o >>= 1) s0p += __shfl_xor_sync(FULL, s0p, o);
    float s0 = s0p + sb00;
    __syncwarp();

    // B-chunk cooperative load indices (16x160 floats = 640 float4)
    int i1 = t + 256, i2 = t + 512;
    int b0r = t / 40,  b0c = (t % 40) * 4;
    int b1r = i1 / 40, b1c = (i1 % 40) * 4;
    int b2r = i2 / 40, b2c = (i2 % 40) * 4;

    // ---- mini-GEMM 0: U[w] = sQ[w] @ Mt + m0 ----
    {
        float acc[5] = {0.f, 0.f, 0.f, 0.f, 0.f};
        float4 pb0 = *(const float4*)&g_Mt[b0r * DD + b0c];
        float4 pb1 = *(const float4*)&g_Mt[b1r * DD + b1c];
        float4 pb2;
        if (t < 128) pb2 = *(const float4*)&g_Mt[b2r * DD + b2c];
        *(float4*)&sBs[0][b0r][b0c] = pb0;
        *(float4*)&sBs[0][b1r][b1c] = pb1;
        if (t < 128) *(float4*)&sBs[0][b2r][b2c] = pb2;
        for (int c = 0; c < 10; ++c) {
            __syncthreads();
            int cur = c & 1;
            if (c < 9) {
                int g0 = (c + 1) * 16;
                pb0 = *(const float4*)&g_Mt[(g0 + b0r) * DD + b0c];
                pb1 = *(const float4*)&g_Mt[(g0 + b1r) * DD + b1c];
                if (t < 128) pb2 = *(const float4*)&g_Mt[(g0 + b2r) * DD + b2c];
            }
#pragma unroll
            for (int g = 0; g < 16; ++g) {
                float av = sQ[w][c * 16 + g];
#pragma unroll
                for (int j = 0; j < 5; ++j)
                    acc[j] = fmaf(av, sBs[cur][g][lane + 32 * j], acc[j]);
            }
            if (c < 9) {
                int nb = 1 - cur;
                *(float4*)&sBs[nb][b0r][b0c] = pb0;
                *(float4*)&sBs[nb][b1r][b1c] = pb1;
                if (t < 128) *(float4*)&sBs[nb][b2r][b2c] = pb2;
            }
        }
#pragma unroll
        for (int j = 0; j < 5; ++j)
            sU[w][lane + 32 * j] = acc[j] + g_m0[lane + 32 * j];
    }
    __syncwarp();

    // ---- phase2: two-pass softmax attention (warp-autonomous, no block syncs) ----
    int ids0 = nbr_ids[b * KK + lane];
    int ids1 = nbr_ids[b * KK + 32 + lane];
    int ets0 = etime[b * KK + lane];
    int ets1 = etime[b * KK + 32 + lane];
    float gu0 = gum[b * KK + lane];
    float gu1 = gum[b * KK + 32 + lane];

    float4 u4 = ((const float4*)sU[w])[lane];
    float4 ut4 = make_float4(0.f, 0.f, 0.f, 0.f);
    if (lane < 8) ut4 = ((const float4*)sU[w])[32 + lane];

    float sc0 = 0.f, sc1 = 0.f;

    // pass A: all 64 scores, fully independent batches
#pragma unroll
    for (int j = 0; j < 16; ++j) {
        int kk = (4 * j) & 31;
        int idreg = (j < 8) ? ids0 : ids1;
        int etreg = (j < 8) ? ets0 : ets1;
        int nid[4], etv[4];
#pragma unroll
        for (int i = 0; i < 4; ++i) {
            nid[i] = __shfl_sync(FULL, idreg, kk + i);
            etv[i] = __shfl_sync(FULL, etreg, kk + i);
        }
        float4 xr[4], tr[4];
#pragma unroll
        for (int i = 0; i < 4; ++i) xr[i] = xv[nid[i] * 32 + lane];
#pragma unroll
        for (int i = 0; i < 4; ++i)
            tr[i] = (lane < 8) ? tv[etv[i] * 8 + lane] : make_float4(0.f, 0.f, 0.f, 0.f);

        float p[4];
#pragma unroll
        for (int i = 0; i < 4; ++i)
            p[i] = u4.x * xr[i].x + u4.y * xr[i].y + u4.z * xr[i].z + u4.w * xr[i].w
                 + ut4.x * tr[i].x + ut4.y * tr[i].y + ut4.z * tr[i].z + ut4.w * tr[i].w;

        p[0] += __shfl_xor_sync(FULL, p[0], 1);
        p[1] += __shfl_xor_sync(FULL, p[1], 1);
        p[2] += __shfl_xor_sync(FULL, p[2], 1);
        p[3] += __shfl_xor_sync(FULL, p[3], 1);
        float ra = (lane & 1) ? p[1] : p[0];
        float rb = (lane & 1) ? p[3] : p[2];
#pragma unroll
        for (int o = 2; o <= 16; o <<= 1) {
            ra += __shfl_xor_sync(FULL, ra, o);
            rb += __shfl_xor_sync(FULL, rb, o);
        }
        // owner lanes kk..kk+3 already hold their own full sums
        int rel = lane - kk;
        if (rel >= 0 && rel < 4) {
            float sv = ((rel < 2) ? ra : rb) + s0;
            if (j < 8) sc0 = sv; else sc1 = sv;
        }
    }

    // softmax over 64 scores (2 per lane)
    float m = fmaxf(sc0, sc1);
#pragma unroll
    for (int o = 16; o; o >>= 1) m = fmaxf(m, __shfl_xor_sync(FULL, m, o));
    float e0 = expf(sc0 - m), e1 = expf(sc1 - m);
    float s = e0 + e1;
#pragma unroll
    for (int o = 16; o; o >>= 1) s += __shfl_xor_sync(FULL, s, o);
    float inv = 1.f / s;
    float aw0 = e0 * inv, aw1 = e1 * inv;

    // gumbel mask
    float g0 = -logf(-logf(gu0 + 1e-10f) + 1e-10f);
    float g1 = -logf(-logf(gu1 + 1e-10f) + 1e-10f);
    float z0 = aw0 + g0, z1 = aw1 + g1;
    float zm = fmaxf(z0, z1);
#pragma unroll
    for (int o = 16; o; o >>= 1) zm = fmaxf(zm, __shfl_xor_sync(FULL, zm, o));
    float ez0 = expf(z0 - zm), ez1 = expf(z1 - zm);
    float zs = ez0 + ez1;
#pragma unroll
    for (int o = 16; o; o >>= 1) zs += __shfl_xor_sync(FULL, zs, o);
    out_mask[b * KK + lane]      = (ez0 / zs > 0.2f) ? 1.0f : 0.0f;
    out_mask[b * KK + 32 + lane] = (ez1 / zs > 0.2f) ? 1.0f : 0.0f;

    // pass B: weighted accumulation (rows L2-hot)
    float4 ax = make_float4(0.f, 0.f, 0.f, 0.f);
    float4 at = make_float4(0.f, 0.f, 0.f, 0.f);
#pragma unroll
    for (int j = 0; j < 16; ++j) {
        int kk = (4 * j) & 31;
        int idreg = (j < 8) ? ids0 : ids1;
        int etreg = (j < 8) ? ets0 : ets1;
        float awreg = (j < 8) ? aw0 : aw1;
        int nid[4], etv[4];
        float wv[4];
#pragma unroll
        for (int i = 0; i < 4; ++i) {
            nid[i] = __shfl_sync(FULL, idreg, kk + i);
            etv[i] = __shfl_sync(FULL, etreg, kk + i);
            wv[i]  = __shfl_sync(FULL, awreg, kk + i);
        }
        float4 xr[4], tr[4];
#pragma unroll
        for (int i = 0; i < 4; ++i) xr[i] = xv[nid[i] * 32 + lane];
#pragma unroll
        for (int i = 0; i < 4; ++i)
            tr[i] = (lane < 8) ? tv[etv[i] * 8 + lane] : make_float4(0.f, 0.f, 0.f, 0.f);
#pragma unroll
        for (int i = 0; i < 4; ++i) {
            ax.x = fmaf(wv[i], xr[i].x, ax.x);
            ax.y = fmaf(wv[i], xr[i].y, ax.y);
            ax.z = fmaf(wv[i], xr[i].z, ax.z);
            ax.w = fmaf(wv[i], xr[i].w, ax.w);
            at.x = fmaf(wv[i], tr[i].x, at.x);
            at.y = fmaf(wv[i], tr[i].y, at.y);
            at.z = fmaf(wv[i], tr[i].z, at.z);
            at.w = fmaf(wv[i], tr[i].w, at.w);
        }
    }

    // stash Acc row in recycled sQ buffer (warp-private)
    ((float4*)sQ[w])[lane] = ax;
    if (lane < 8) ((float4*)sQ[w])[32 + lane] = at;

    __syncthreads();   // all warps past gemm-0 B reads before refilling sBs

    // ---- mini-GEMM 1: attn_out[b] = Acc[w] @ Pt + p0, fused mlp epilogue ----
    {
        float acc[5] = {0.f, 0.f, 0.f, 0.f, 0.f};
        float4 pb0 = *(const float4*)&g_Pt[b0r * DD + b0c];
        float4 pb1 = *(const float4*)&g_Pt[b1r * DD + b1c];
        float4 pb2;
        if (t < 128) pb2 = *(const float4*)&g_Pt[b2r * DD + b2c];
        *(float4*)&sBs[0][b0r][b0c] = pb0;
        *(float4*)&sBs[0][b1r][b1c] = pb1;
        if (t < 128) *(float4*)&sBs[0][b2r][b2c] = pb2;
        for (int c = 0; c < 10; ++c) {
            __syncthreads();
            int cur = c & 1;
            if (c < 9) {
                int g0 = (c + 1) * 16;
                pb0 = *(const float4*)&g_Pt[(g0 + b0r) * DD + b0c];
                pb1 = *(const float4*)&g_Pt[(g0 + b1r) * DD + b1c];
                if (t < 128) pb2 = *(const float4*)&g_Pt[(g0 + b2r) * DD + b2c];
            }
#pragma unroll
            for (int g = 0; g < 16; ++g) {
                float av = sQ[w][c * 16 + g];
#pragma unroll
                for (int j = 0; j < 5; ++j)
                    acc[j] = fmaf(av, sBs[cur][g][lane + 32 * j], acc[j]);
            }
            if (c < 9) {
                int nb = 1 - cur;
                *(float4*)&sBs[nb][b0r][b0c] = pb0;
                *(float4*)&sBs[nb][b1r][b1c] = pb1;
                if (t < 128) *(float4*)&sBs[nb][b2r][b2c] = pb2;
            }
        }
        // epilogue: bias, store attn_out, warp-local mlp dot + leaky edges
        float md = 0.f;
        float cb[5];
#pragma unroll
        for (int j = 0; j < 5; ++j) {
            cb[j] = acc[j] + g_p0[lane + 32 * j];
            out1[b * DD + lane + 32 * j] = cb[j];
            md = fmaf(cb[j], smlp[lane + 32 * j], md);
        }
#pragma unroll
        for (int o = 16; o; o >>= 1) md += __shfl_xor_sync(FULL, md, o);
        float wE = smlp[DD], bE = smlp[DD + 1];
#pragma unroll
        for (int q = 0; q < 2; ++q) {
            int k = lane + 32 * q;
            float v = md + fmaf(ew[b * KK + k], wE, bE);
            out2[b * KK + k] = (v >= 0.f) ? v : 0.01f * v;
        }
    }
}

// ---------------- launch ----------------------------------------------------------
extern "C" void kernel_launch(void* const* d_in, const int* in_sizes, int n_in,
                              void* d_out, int out_size) {
    const float* x    = (const float*)d_in[0];
    const int*   tgt  = (const int*)  d_in[1];
    const int*   tt   = (const int*)  d_in[2];
    const int*   nbr  = (const int*)  d_in[3];
    const int*   et   = (const int*)  d_in[4];
    const float* ew   = (const float*)d_in[5];
    const float* gu   = (const float*)d_in[6];
    const float* tew  = (const float*)d_in[7];
    const float* teb  = (const float*)d_in[8];
    const float* ipw  = (const float*)d_in[9];
    const float* ipb  = (const float*)d_in[10];
    const float* outw = (const float*)d_in[11];
    const float* outb = (const float*)d_in[12];
    const float* mlpw = (const float*)d_in[13];
    const float* mlpb = (const float*)d_in[14];

    float* o1 = (float*)d_out;           // attn_output     [B, D]
    float* o2 = o1 + BB * DD;            // new_edge_weight [B, K]
    float* o3 = o2 + BB * KK;            // candidate_mask  [B, K]

    int tbl_blks = (NT * TE + 255) / 256;
    setup_kernel<<<PREP_BLKS + tbl_blks, 256>>>(ipw, ipb, outw, outb, tew, teb);
    fused_kernel<<<BB / 8, 256>>>(x, tgt, tt, nbr, et, gu, ew, mlpw, mlpb, o1, o2, o3);
}

// round 14
// speedup vs baseline: 1.2412x; 1.2412x over previous
#include <cuda_runtime.h>
#include <math.h>

// Problem constants
#define BB 4096
#define KK 64
#define FF 128
#define TE 32
#define DD 160
#define NT 10000
#define INV_SQRT_D 0.07905694150420949f   // 1/sqrt(160)
#define FULL 0xffffffffu

// ---------------- scratch (__device__ globals) ----------------------------------
__device__ __align__(16) float g_tbl[NT * TE];   // cos(t*w+b) table
__device__ __align__(16) float g_Mt[DD * DD];    // Mt[g][o] = (Wk^T Wq / sqrt(D))[o][g]
__device__ __align__(16) float g_Pt[DD * DD];    // Pt[g][e] = (out_w @ Wv)[e][g]
__device__ float g_m0[DD];
__device__ float g_w0[DD];
__device__ float g_p0[DD];
__device__ float g_b00[1];
__device__ __align__(16) float g_U[BB * DD];     // transformed queries
__device__ float g_S0[BB];                       // score bias
__device__ __align__(16) float g_Acc[BB * DD];   // attn-weighted kv accumulation

// ---------------- kernel 0: fold weights + cos table (merged) --------------------
#define PREP_BLKS (2 * DD + 1)
__global__ void __launch_bounds__(256)
setup_kernel(const float* __restrict__ ipw,
             const float* __restrict__ ipb,
             const float* __restrict__ outw,
             const float* __restrict__ outb,
             const float* __restrict__ tw,
             const float* __restrict__ tb) {
    int bidx = blockIdx.x;
    int t = threadIdx.x;
    if (bidx < PREP_BLKS) {
        if (t >= DD) return;
        if (bidx < DD) {
            int f = bidx;
            float acc = 0.f;
            for (int d = 0; d < DD; ++d)
                acc = fmaf(ipw[(DD + d) * DD + f], ipw[d * DD + t], acc);
            g_Mt[t * DD + f] = acc * INV_SQRT_D;           // transposed
        } else if (bidx < 2 * DD) {
            int e = bidx - DD;
            float acc = 0.f;
            for (int d = 0; d < DD; ++d)
                acc = fmaf(outw[e * DD + d], ipw[(2 * DD + d) * DD + t], acc);
            g_Pt[t * DD + e] = acc;                        // transposed
        } else {
            float m0 = 0.f, w0 = 0.f, p0 = 0.f;
            for (int d = 0; d < DD; ++d) {
                m0 = fmaf(ipw[(DD + d) * DD + t], ipb[d], m0);
                w0 = fmaf(ipw[d * DD + t], ipb[DD + d], w0);
                p0 = fmaf(outw[t * DD + d], ipb[2 * DD + d], p0);
            }
            g_m0[t] = m0 * INV_SQRT_D;
            g_w0[t] = w0 * INV_SQRT_D;
            g_p0[t] = p0 + outb[t];
            if (t == 0) {
                float b00 = 0.f;
                for (int d = 0; d < DD; ++d) b00 = fmaf(ipb[d], ipb[DD + d], b00);
                g_b00[0] = b00 * INV_SQRT_D;
            }
        }
    } else {
        int idx = (bidx - PREP_BLKS) * 256 + t;
        if (idx >= NT * TE) return;
        int tt = idx >> 5;
        int j = idx & 31;
        float arg = __fadd_rn(__fmul_rn((float)tt, tw[j]), tb[j]);
        float kf = rintf(arg * 0.15915494309189535f);
        double r = fma(-(double)kf, 6.283185307179586, (double)arg);
        g_tbl[idx] = cosf((float)r);
    }
}

// ---------------- fused GEMM: 16b x 160o tile, 256 blocks x 256 thr --------------
// PH0: A = gather(x, tbl) by target ids; C = g_U; side-product S0.
// PH1: A = g_Acc; C = out1 (attn_out); fused mlp-dot + leaky edge weights.
template <int PH>
__global__ void __launch_bounds__(256)
gemm_kernel(const float* __restrict__ x,
            const int* __restrict__ tgt_ids,
            const int* __restrict__ tgt_times,
            const float* __restrict__ ew,
            const float* __restrict__ mlpw,
            const float* __restrict__ mlpb,
            float* __restrict__ out1,
            float* __restrict__ out2) {
    __shared__ float As[2][16][16];
    __shared__ float Bs[2][16][DD];
    __shared__ float sw0[DD];
    __shared__ int   stg[16], stt[16];
    __shared__ float smlp[DD + 2];

    const float* Bt   = (PH == 0) ? g_Mt : g_Pt;
    const float* bias = (PH == 0) ? g_m0 : g_p0;

    int t = threadIdx.x;
    int ox = t & 31, by = t >> 5;        // warp 0..7
    int b0 = blockIdx.x * 16;

    if (PH == 0) {
        if (t < DD) sw0[t] = g_w0[t];
        if (t < 16) { stg[t] = tgt_ids[b0 + t]; stt[t] = tgt_times[b0 + t]; }
    } else {
        if (t < DD + 1) smlp[t] = mlpw[t];
        if (t == 0) smlp[DD + 1] = mlpb[0];
    }
    __syncthreads();

    int ar = t >> 4, ac = t & 15;
    int tg = 0, ttm = 0;
    if (PH == 0) { tg = stg[ar]; ttm = stt[ar]; }

    int i1 = t + 256, i2 = t + 512;
    int b0r = t / 40,  b0c = (t % 40) * 4;
    int b1r = i1 / 40, b1c = (i1 % 40) * 4;
    int b2r = i2 / 40, b2c = (i2 % 40) * 4;

    float acc[2][5];
#pragma unroll
    for (int i = 0; i < 2; ++i)
#pragma unroll
        for (int j = 0; j < 5; ++j) acc[i][j] = 0.f;
    float s0p = 0.f;

    float va;
    float4 pb0, pb1, pb2;

    // prologue chunk 0
    if (PH == 0)
        va = (ac < FF) ? x[tg * FF + ac] : g_tbl[ttm * TE + (ac - FF)];
    else
        va = g_Acc[(b0 + ar) * DD + ac];
    if (PH == 0) s0p = va * sw0[ac];
    pb0 = *(const float4*)&Bt[b0r * DD + b0c];
    pb1 = *(const float4*)&Bt[b1r * DD + b1c];
    if (t < 128) pb2 = *(const float4*)&Bt[b2r * DD + b2c];
    As[0][ar][ac] = va;
    *(float4*)&Bs[0][b0r][b0c] = pb0;
    *(float4*)&Bs[0][b1r][b1c] = pb1;
    if (t < 128) *(float4*)&Bs[0][b2r][b2c] = pb2;

    for (int c = 0; c < 10; ++c) {
        __syncthreads();
        int cur = c & 1;
        if (c < 9) {
            int g0 = (c + 1) * 16;
            int g = g0 + ac;
            if (PH == 0)
                va = (g < FF) ? x[tg * FF + g] : g_tbl[ttm * TE + (g - FF)];
            else
                va = g_Acc[(b0 + ar) * DD + g];
            if (PH == 0) s0p = fmaf(va, sw0[g], s0p);
            pb0 = *(const float4*)&Bt[(g0 + b0r) * DD + b0c];
            pb1 = *(const float4*)&Bt[(g0 + b1r) * DD + b1c];
            if (t < 128) pb2 = *(const float4*)&Bt[(g0 + b2r) * DD + b2c];
        }
#pragma unroll
        for (int g = 0; g < 16; ++g) {
            float av0 = As[cur][by][g];
            float av1 = As[cur][by + 8][g];
            float bv[5];
#pragma unroll
            for (int j = 0; j < 5; ++j) bv[j] = Bs[cur][g][ox + 32 * j];
#pragma unroll
            for (int j = 0; j < 5; ++j) {
                acc[0][j] = fmaf(av0, bv[j], acc[0][j]);
                acc[1][j] = fmaf(av1, bv[j], acc[1][j]);
            }
        }
        if (c < 9) {
            int nb = 1 - cur;
            As[nb][ar][ac] = va;
            *(float4*)&Bs[nb][b0r][b0c] = pb0;
            *(float4*)&Bs[nb][b1r][b1c] = pb1;
            if (t < 128) *(float4*)&Bs[nb][b2r][b2c] = pb2;
        }
    }

    float bi[5];
#pragma unroll
    for (int j = 0; j < 5; ++j) bi[j] = bias[ox + 32 * j];

    if (PH == 0) {
#pragma unroll
        for (int i = 0; i < 2; ++i)
#pragma unroll
            for (int j = 0; j < 5; ++j)
                g_U[(b0 + by + 8 * i) * DD + ox + 32 * j] = acc[i][j] + bi[j];
        // S0: reduce over the 16 threads of each row (16-lane segments)
#pragma unroll
        for (int off = 8; off; off >>= 1)
            s0p += __shfl_down_sync(FULL, s0p, off, 16);
        if (ac == 0) g_S0[b0 + ar] = s0p + g_b00[0];
    } else {
        float cb[2][5];
        float md0 = 0.f, md1 = 0.f;
#pragma unroll
        for (int j = 0; j < 5; ++j) {
            cb[0][j] = acc[0][j] + bi[j];
            cb[1][j] = acc[1][j] + bi[j];
            float mw = smlp[ox + 32 * j];
            md0 = fmaf(cb[0][j], mw, md0);
            md1 = fmaf(cb[1][j], mw, md1);
        }
#pragma unroll
        for (int i = 0; i < 2; ++i)
#pragma unroll
            for (int j = 0; j < 5; ++j)
                out1[(b0 + by + 8 * i) * DD + ox + 32 * j] = cb[i][j];
        // warp holds complete rows by and by+8 -> reduce mlp dot in-warp
        md0 += __shfl_xor_sync(FULL, md0, 1);
        md1 += __shfl_xor_sync(FULL, md1, 1);
        float ra = (ox & 1) ? md1 : md0;
#pragma unroll
        for (int o = 2; o <= 16; o <<= 1) ra += __shfl_xor_sync(FULL, ra, o);
        float m0 = __shfl_sync(FULL, ra, 0);   // row by
        float m1 = __shfl_sync(FULL, ra, 1);   // row by+8
        float wE = smlp[DD], bE = smlp[DD + 1];
#pragma unroll
        for (int rr = 0; rr < 2; ++rr) {
            int row = b0 + by + 8 * rr;
            float mm = rr ? m1 : m0;
#pragma unroll
            for (int q = 0; q < 2; ++q) {
                int k = ox + 32 * q;
                float v = mm + fmaf(ew[row * KK + k], wE, bE);
                out2[row * KK + k] = (v >= 0.f) ? v : 0.01f * v;
            }
        }
    }
}

// ---------------- phase2: warp-per-target SINGLE-PASS max-free softmax -----------
// Each row gathered exactly once (half the L2 traffic of two-pass). Scores are
// O(1) so exp(score) without max subtraction is safe and mathematically equal
// to the reference softmax. Batches are fully independent: no max-rescale chain;
// the only cross-batch dependency is the plain FMA accumulator.
__global__ void __launch_bounds__(256)
phase2_kernel(const float* __restrict__ x,
              const int* __restrict__ nbr_ids,
              const int* __restrict__ etime,
              const float* __restrict__ gum,
              float* __restrict__ out_mask) {
    int t = threadIdx.x, w = t >> 5, lane = t & 31;
    int b = blockIdx.x * 8 + w;

    const float4* xv = (const float4*)x;
    const float4* tv = (const float4*)g_tbl;
    const float4* uv = (const float4*)g_U;

    int ids0 = nbr_ids[b * KK + lane];
    int ids1 = nbr_ids[b * KK + 32 + lane];
    int ets0 = etime[b * KK + lane];
    int ets1 = etime[b * KK + 32 + lane];
    float gu0 = gum[b * KK + lane];
    float gu1 = gum[b * KK + 32 + lane];

    float4 u4 = uv[b * 40 + lane];
    float4 ut4 = make_float4(0.f, 0.f, 0.f, 0.f);
    if (lane < 8) ut4 = uv[b * 40 + 32 + lane];
    float s0 = g_S0[b];

    float sc0 = 0.f, sc1 = 0.f;            // stashed raw scores (owner lanes)
    float4 ax = make_float4(0.f, 0.f, 0.f, 0.f);
    float4 at = make_float4(0.f, 0.f, 0.f, 0.f);

#pragma unroll
    for (int j = 0; j < 16; ++j) {
        int kk = (4 * j) & 31;
        int idreg = (j < 8) ? ids0 : ids1;
        int etreg = (j < 8) ? ets0 : ets1;
        int nid[4], etv[4];
#pragma unroll
        for (int i = 0; i < 4; ++i) {
            nid[i] = __shfl_sync(FULL, idreg, kk + i);
            etv[i] = __shfl_sync(FULL, etreg, kk + i);
        }
        float4 xr[4], tr[4];
#pragma unroll
        for (int i = 0; i < 4; ++i) xr[i] = xv[nid[i] * 32 + lane];
#pragma unroll
        for (int i = 0; i < 4; ++i)
            tr[i] = (lane < 8) ? tv[etv[i] * 8 + lane] : make_float4(0.f, 0.f, 0.f, 0.f);

        float p[4];
#pragma unroll
        for (int i = 0; i < 4; ++i)
            p[i] = u4.x * xr[i].x + u4.y * xr[i].y + u4.z * xr[i].z + u4.w * xr[i].w
                 + ut4.x * tr[i].x + ut4.y * tr[i].y + ut4.z * tr[i].z + ut4.w * tr[i].w;

        p[0] += __shfl_xor_sync(FULL, p[0], 1);
        p[1] += __shfl_xor_sync(FULL, p[1], 1);
        p[2] += __shfl_xor_sync(FULL, p[2], 1);
        p[3] += __shfl_xor_sync(FULL, p[3], 1);
        float ra = (lane & 1) ? p[1] : p[0];
        float rb = (lane & 1) ? p[3] : p[2];
#pragma unroll
        for (int o = 2; o <= 16; o <<= 1) {
            ra += __shfl_xor_sync(FULL, ra, o);
            rb += __shfl_xor_sync(FULL, rb, o);
        }
        // owner lanes kk..kk+3 hold their own full sums; stash score, compute exp
        int rel = lane - kk;
        float myscore = ((rel == 0 || rel == 1) ? ra : rb) + s0;   // valid on owners
        if (rel >= 0 && rel < 4) {
            if (j < 8) sc0 = myscore; else sc1 = myscore;
        }
        float eo = expf(myscore);          // garbage on non-owners (unused)
        float e[4];
        e[0] = __shfl_sync(FULL, eo, kk);
        e[1] = __shfl_sync(FULL, eo, kk + 1);
        e[2] = __shfl_sync(FULL, eo, kk + 2);
        e[3] = __shfl_sync(FULL, eo, kk + 3);
#pragma unroll
        for (int i = 0; i < 4; ++i) {
            ax.x = fmaf(e[i], xr[i].x, ax.x);
            ax.y = fmaf(e[i], xr[i].y, ax.y);
            ax.z = fmaf(e[i], xr[i].z, ax.z);
            ax.w = fmaf(e[i], xr[i].w, ax.w);
            at.x = fmaf(e[i], tr[i].x, at.x);
            at.y = fmaf(e[i], tr[i].y, at.y);
            at.z = fmaf(e[i], tr[i].z, at.z);
            at.w = fmaf(e[i], tr[i].w, at.w);
        }
    }

    // normalization: sum of exp from stashed scores (bit-identical recompute)
    float e0 = expf(sc0), e1 = expf(sc1);
    float s = e0 + e1;
#pragma unroll
    for (int o = 16; o; o >>= 1) s += __shfl_xor_sync(FULL, s, o);
    float inv = 1.f / s;

    float4 o4;
    o4.x = ax.x * inv; o4.y = ax.y * inv; o4.z = ax.z * inv; o4.w = ax.w * inv;
    ((float4*)&g_Acc[b * DD])[lane] = o4;
    if (lane < 8) {
        float4 o8;
        o8.x = at.x * inv; o8.y = at.y * inv; o8.z = at.z * inv; o8.w = at.w * inv;
        ((float4*)&g_Acc[b * DD])[32 + lane] = o8;
    }

    // gumbel mask (attn weights = e/sum, same values as reference softmax)
    float aw0 = e0 * inv, aw1 = e1 * inv;
    float g0 = -logf(-logf(gu0 + 1e-10f) + 1e-10f);
    float g1 = -logf(-logf(gu1 + 1e-10f) + 1e-10f);
    float z0 = aw0 + g0, z1 = aw1 + g1;
    float zm = fmaxf(z0, z1);
#pragma unroll
    for (int o = 16; o; o >>= 1) zm = fmaxf(zm, __shfl_xor_sync(FULL, zm, o));
    float ez0 = expf(z0 - zm), ez1 = expf(z1 - zm);
    float zs = ez0 + ez1;
#pragma unroll
    for (int o = 16; o; o >>= 1) zs += __shfl_xor_sync(FULL, zs, o);
    out_mask[b * KK + lane]      = (ez0 / zs > 0.2f) ? 1.0f : 0.0f;
    out_mask[b * KK + 32 + lane] = (ez1 / zs > 0.2f) ? 1.0f : 0.0f;
}

// ---------------- launch ----------------------------------------------------------
extern "C" void kernel_launch(void* const* d_in, const int* in_sizes, int n_in,
                              void* d_out, int out_size) {
    const float* x    = (const float*)d_in[0];
    const int*   tgt  = (const int*)  d_in[1];
    const int*   tt   = (const int*)  d_in[2];
    const int*   nbr  = (const int*)  d_in[3];
    const int*   et   = (const int*)  d_in[4];
    const float* ew   = (const float*)d_in[5];
    const float* gu   = (const float*)d_in[6];
    const float* tew  = (const float*)d_in[7];
    const float* teb  = (const float*)d_in[8];
    const float* ipw  = (const float*)d_in[9];
    const float* ipb  = (const float*)d_in[10];
    const float* outw = (const float*)d_in[11];
    const float* outb = (const float*)d_in[12];
    const float* mlpw = (const float*)d_in[13];
    const float* mlpb = (const float*)d_in[14];

    float* o1 = (float*)d_out;           // attn_output     [B, D]
    float* o2 = o1 + BB * DD;            // new_edge_weight [B, K]
    float* o3 = o2 + BB * KK;            // candidate_mask  [B, K]

    int tbl_blks = (NT * TE + 255) / 256;
    setup_kernel<<<PREP_BLKS + tbl_blks, 256>>>(ipw, ipb, outw, outb, tew, teb);
    // gemm<0>: fused gather + Qin@M^T + S0  -> g_U, g_S0
    gemm_kernel<0><<<256, 256>>>(x, tgt, tt, nullptr, nullptr, nullptr, nullptr, nullptr);
    phase2_kernel<<<BB / 8, 256>>>(x, nbr, et, gu, o3);
    // gemm<1>: Acc@P^T + p0 -> attn_out, fused mlp + leaky edge weights
    gemm_kernel<1><<<256, 256>>>(nullptr, nullptr, nullptr, ew, mlpw, mlpb, o1, o2);
}